// round 1
// baseline (speedup 1.0000x reference)
#include <cuda_runtime.h>
#include <cstdint>

// ---------------- problem dims ----------------
#define NB 64
#define L1_IN 16000
#define C1 128
#define K1 84
#define L1 3980         // conv1 out
#define P1 1990         // pool1 out
#define C2 128
#define K2 4
#define L2 1991
#define P2 995
#define C3 256
#define K3 4
#define L3 994
#define P3 497
#define C5 512
#define K5 3
#define L5 499
#define P5 249
#define NCLS 35
#define NSLICE 256

// ---------------- scratch (device globals; no runtime allocation) ----------------
__device__ float   g_w1q[C1 * K1];                 // signed +-0.1
__device__ int8_t  g_w2p[C2 * K2 * C2];            // [co][k][ci]
__device__ int8_t  g_w3p[C3 * K3 * C2];            // [256][4][128]
__device__ int8_t  g_w5p[C5 * K5 * C3];            // [512][3][256]
__device__ int8_t  g_wfcp[NCLS * P5 * C5];         // [35][t][c]

__device__ float   g_h1[(size_t)NB * L1 * C1];     // [n][t][c]
__device__ float   g_h2[(size_t)NB * L2 * C2];
__device__ float   g_h3[(size_t)NB * L3 * C3];
__device__ float   g_h5[(size_t)NB * L5 * C5];
__device__ int8_t  g_a1[(size_t)NB * P1 * C1];     // +-1, [n][t][c]
__device__ int8_t  g_a2[(size_t)NB * P2 * C2];
__device__ int8_t  g_a3[(size_t)NB * P3 * C3];
__device__ int8_t  g_a5[(size_t)NB * P5 * C5];

__device__ double  g_psum[512 * NSLICE];
__device__ double  g_psq [512 * NSLICE];
__device__ float   g_scale[512];
__device__ float   g_shift[512];

// ---------------- weight prep ----------------
__global__ void k_prep_w1(const float* __restrict__ w1) {
    int i = blockIdx.x * blockDim.x + threadIdx.x;
    if (i < C1 * K1) g_w1q[i] = (w1[i] >= 0.f) ? 0.1f : -0.1f;
}

// w[co][ci][k] (OIHW, W=1) -> p[co][k][ci] as +-1 int8
__global__ void k_prep_wc(const float* __restrict__ w, int8_t* __restrict__ p,
                          int Cout, int Cin, int K) {
    int i = blockIdx.x * blockDim.x + threadIdx.x;
    int tot = Cout * Cin * K;
    if (i >= tot) return;
    int co = i / (Cin * K);
    int r  = i % (Cin * K);
    int ci = r / K;
    int k  = r % K;
    p[((size_t)co * K + k) * Cin + ci] = (w[i] >= 0.f) ? (int8_t)1 : (int8_t)-1;
}

// wfc[m][c*P5 + t] -> g_wfcp[m][t][c]
__global__ void k_prep_wfc(const float* __restrict__ w) {
    int i = blockIdx.x * blockDim.x + threadIdx.x;
    if (i >= NCLS * P5 * C5) return;
    int m = i / (P5 * C5);
    int r = i % (P5 * C5);          // r = c*P5 + t
    int c = r / P5;
    int t = r % P5;
    g_wfcp[((size_t)m * P5 + t) * C5 + c] = (w[i] >= 0.f) ? (int8_t)1 : (int8_t)-1;
}

// ---------------- conv1: fp32, stride 4, K=84, no pad ----------------
// block: 256 threads; tile 128c x 32t; thread tile 4c x 4t
__global__ __launch_bounds__(256) void k_conv1(const float* __restrict__ x,
                                               const float* __restrict__ b1) {
    __shared__ float ws2[K1 * C1];       // [k][c]   43 KB
    __shared__ float xs[208];            // 4*31+84
    int n  = blockIdx.y;
    int tb = blockIdx.x * 32;
    int tid = threadIdx.x;

    for (int i = tid; i < C1 * K1; i += 256) {
        int c = i / K1, k = i % K1;
        ws2[k * C1 + c] = g_w1q[i];
    }
    int x0 = tb * 4;
    for (int i = tid; i < 208; i += 256) {
        int xi = x0 + i;
        xs[i] = (xi < L1_IN) ? x[(size_t)n * L1_IN + xi] : 0.f;
    }
    __syncthreads();

    int cg = tid & 31;
    int tg = tid >> 5;
    int c0 = cg * 4;
    int t0 = tg * 4;

    float acc[4][4] = {};
#pragma unroll 4
    for (int k = 0; k < K1; k++) {
        float4 wv = *reinterpret_cast<const float4*>(&ws2[k * C1 + c0]);
#pragma unroll
        for (int i = 0; i < 4; i++) {
            float xv = xs[(t0 + i) * 4 + k];
            acc[0][i] += wv.x * xv;
            acc[1][i] += wv.y * xv;
            acc[2][i] += wv.z * xv;
            acc[3][i] += wv.w * xv;
        }
    }
    float4 bb = *reinterpret_cast<const float4*>(&b1[c0]);
#pragma unroll
    for (int i = 0; i < 4; i++) {
        int t = tb + t0 + i;
        if (t < L1) {
            float4 v = make_float4(acc[0][i] + bb.x, acc[1][i] + bb.y,
                                   acc[2][i] + bb.z, acc[3][i] + bb.w);
            *reinterpret_cast<float4*>(&g_h1[((size_t)n * L1 + t) * C1 + c0]) = v;
        }
    }
}

// ---------------- BN stats (deterministic two-stage) ----------------
// stage1: grid = NSLICE blocks, blockDim = C. Each block reduces a fixed row slice.
__global__ void k_stat1(const float* __restrict__ h, int C, int R) {
    int c = threadIdx.x;
    int s = blockIdx.x;
    int rps = (R + NSLICE - 1) / NSLICE;
    int r0 = s * rps;
    int r1 = min(R, r0 + rps);
    float s0 = 0.f, s1 = 0.f, s2 = 0.f, s3 = 0.f;
    float q0 = 0.f, q1 = 0.f, q2 = 0.f, q3 = 0.f;
    int r = r0;
    for (; r + 3 < r1; r += 4) {
        float v0 = h[(size_t)(r + 0) * C + c];
        float v1 = h[(size_t)(r + 1) * C + c];
        float v2 = h[(size_t)(r + 2) * C + c];
        float v3 = h[(size_t)(r + 3) * C + c];
        s0 += v0; q0 += v0 * v0;
        s1 += v1; q1 += v1 * v1;
        s2 += v2; q2 += v2 * v2;
        s3 += v3; q3 += v3 * v3;
    }
    for (; r < r1; r++) {
        float v = h[(size_t)r * C + c];
        s0 += v; q0 += v * v;
    }
    g_psum[c * NSLICE + s] = (double)s0 + (double)s1 + (double)s2 + (double)s3;
    g_psq [c * NSLICE + s] = (double)q0 + (double)q1 + (double)q2 + (double)q3;
}

// stage2: grid = C blocks, blockDim = NSLICE. Produces per-channel scale/shift.
__global__ void k_stat2(const float* __restrict__ gamma, const float* __restrict__ beta,
                        int R) {
    __shared__ double ssum[NSLICE];
    __shared__ double ssq[NSLICE];
    int c = blockIdx.x, t = threadIdx.x;
    ssum[t] = g_psum[c * NSLICE + t];
    ssq[t]  = g_psq [c * NSLICE + t];
    __syncthreads();
    for (int o = NSLICE / 2; o > 0; o >>= 1) {
        if (t < o) { ssum[t] += ssum[t + o]; ssq[t] += ssq[t + o]; }
        __syncthreads();
    }
    if (t == 0) {
        double mu  = ssum[0] / (double)R;
        double var = ssq[0] / (double)R - mu * mu;
        double inv = rsqrt(var + 1e-5);
        double sc  = inv * (double)gamma[c];
        g_scale[c] = (float)sc;
        g_shift[c] = (float)((double)beta[c] - mu * sc);
    }
}

// ---------------- BN + binarize + maxpool(2) ----------------
// h [n][L][C] fp32 -> a [n][Lo][C] int8 (+-1)
__global__ void k_binpool(const float* __restrict__ h, int8_t* __restrict__ a,
                          int C, int L, int Lo, int total4) {
    int idx = blockIdx.x * blockDim.x + threadIdx.x;
    if (idx >= total4) return;
    int c4 = idx % (C / 4);
    int r  = idx / (C / 4);                 // n*Lo + to
    int n  = r / Lo;
    int to = r % Lo;
    int c  = c4 * 4;
    size_t base0 = ((size_t)n * L + 2 * to) * C + c;
    float4 v0 = *reinterpret_cast<const float4*>(&h[base0]);
    float4 v1 = *reinterpret_cast<const float4*>(&h[base0 + C]);
    float4 sc = *reinterpret_cast<const float4*>(&g_scale[c]);
    float4 sh = *reinterpret_cast<const float4*>(&g_shift[c]);
    char4 o;
    o.x = (v0.x * sc.x + sh.x >= 0.f || v1.x * sc.x + sh.x >= 0.f) ? 1 : -1;
    o.y = (v0.y * sc.y + sh.y >= 0.f || v1.y * sc.y + sh.y >= 0.f) ? 1 : -1;
    o.z = (v0.z * sc.z + sh.z >= 0.f || v1.z * sc.z + sh.z >= 0.f) ? 1 : -1;
    o.w = (v0.w * sc.w + sh.w >= 0.f || v1.w * sc.w + sh.w >= 0.f) ? 1 : -1;
    *reinterpret_cast<char4*>(&a[(size_t)r * C + c]) = o;
}

// ---------------- binary conv (exact, dp4a) ----------------
// a [n][Lin][CIN] int8 (+-1, 0 only via padding bounds), wp [co][K][CIN] int8 (+-1)
// out h[n][t][COUT] = 0.1f*sum + bias
template <int CIN, int COUT, int K, int PAD>
__global__ __launch_bounds__(256) void k_convbin(const int8_t* __restrict__ a,
                                                 const int8_t* __restrict__ wp,
                                                 const float* __restrict__ bias,
                                                 float* __restrict__ h,
                                                 int Lin, int Lout) {
    constexpr int TT   = 64;
    constexpr int TCO  = 64;
    constexpr int CICH = 128;                 // ci chunk (words: 32)
    constexpr int AROW = TT + K - 1;
    __shared__ uint32_t ws2[K * 32 * TCO];    // [k][ci4][co]   <=32KB
    __shared__ uint32_t as_[AROW * 33];       // [row][ci4] padded

    int n   = blockIdx.z;
    int cob = blockIdx.y * TCO;
    int tb  = blockIdx.x * TT;
    int tid = threadIdx.x;

    const uint32_t* ag = reinterpret_cast<const uint32_t*>(a);
    const uint32_t* wg = reinterpret_cast<const uint32_t*>(wp);

    int acc[4][4] = {};
    int co0 = (tid & 15) * 4;
    int t0  = (tid >> 4) * 4;

    for (int cib = 0; cib < CIN; cib += CICH) {
        // weights chunk -> [k][ci4][co]
        for (int i = tid; i < K * 32 * TCO; i += 256) {
            int co  = i & 63;
            int kc  = i >> 6;
            int k   = kc >> 5;
            int ci4 = kc & 31;
            ws2[i] = wg[((size_t)(cob + co) * K + k) * (CIN / 4) + (cib >> 2) + ci4];
        }
        // activation rows (zero pad out of range)
        for (int i = tid; i < AROW * 32; i += 256) {
            int row = i >> 5, ci4 = i & 31;
            int ti = tb + row - PAD;
            uint32_t v = 0;
            if (ti >= 0 && ti < Lin)
                v = ag[((size_t)n * Lin + ti) * (CIN / 4) + (cib >> 2) + ci4];
            as_[row * 33 + ci4] = v;
        }
        __syncthreads();

#pragma unroll 2
        for (int ci4 = 0; ci4 < 32; ci4++) {
#pragma unroll
            for (int k = 0; k < K; k++) {
                uint4 wv = *reinterpret_cast<const uint4*>(&ws2[(k * 32 + ci4) * TCO + co0]);
                int a0 = (int)as_[(t0 + 0 + k) * 33 + ci4];
                int a1 = (int)as_[(t0 + 1 + k) * 33 + ci4];
                int a2 = (int)as_[(t0 + 2 + k) * 33 + ci4];
                int a3 = (int)as_[(t0 + 3 + k) * 33 + ci4];
                acc[0][0] = __dp4a((int)wv.x, a0, acc[0][0]);
                acc[0][1] = __dp4a((int)wv.x, a1, acc[0][1]);
                acc[0][2] = __dp4a((int)wv.x, a2, acc[0][2]);
                acc[0][3] = __dp4a((int)wv.x, a3, acc[0][3]);
                acc[1][0] = __dp4a((int)wv.y, a0, acc[1][0]);
                acc[1][1] = __dp4a((int)wv.y, a1, acc[1][1]);
                acc[1][2] = __dp4a((int)wv.y, a2, acc[1][2]);
                acc[1][3] = __dp4a((int)wv.y, a3, acc[1][3]);
                acc[2][0] = __dp4a((int)wv.z, a0, acc[2][0]);
                acc[2][1] = __dp4a((int)wv.z, a1, acc[2][1]);
                acc[2][2] = __dp4a((int)wv.z, a2, acc[2][2]);
                acc[2][3] = __dp4a((int)wv.z, a3, acc[2][3]);
                acc[3][0] = __dp4a((int)wv.w, a0, acc[3][0]);
                acc[3][1] = __dp4a((int)wv.w, a1, acc[3][1]);
                acc[3][2] = __dp4a((int)wv.w, a2, acc[3][2]);
                acc[3][3] = __dp4a((int)wv.w, a3, acc[3][3]);
            }
        }
        __syncthreads();
    }

    float4 bb = *reinterpret_cast<const float4*>(&bias[cob + co0]);
#pragma unroll
    for (int i = 0; i < 4; i++) {
        int t = tb + t0 + i;
        if (t >= Lout) continue;
        float4 v;
        v.x = 0.1f * (float)acc[0][i] + bb.x;
        v.y = 0.1f * (float)acc[1][i] + bb.y;
        v.z = 0.1f * (float)acc[2][i] + bb.z;
        v.w = 0.1f * (float)acc[3][i] + bb.w;
        *reinterpret_cast<float4*>(&h[((size_t)n * Lout + t) * COUT + cob + co0]) = v;
    }
}

// ---------------- FC: out[n][m] = 0.1f * <a5[n], sign(wfc[m])> ----------------
__global__ __launch_bounds__(256) void k_fc(float* __restrict__ out) {
    int m = blockIdx.x, n = blockIdx.y, tid = threadIdx.x;
    const uint32_t* av = reinterpret_cast<const uint32_t*>(&g_a5[(size_t)n * P5 * C5]);
    const uint32_t* wv = reinterpret_cast<const uint32_t*>(&g_wfcp[(size_t)m * P5 * C5]);
    int s = 0;
    for (int i = tid; i < P5 * C5 / 4; i += 256)
        s = __dp4a((int)av[i], (int)wv[i], s);
    __shared__ int red[256];
    red[tid] = s;
    __syncthreads();
    for (int o = 128; o > 0; o >>= 1) {
        if (tid < o) red[tid] += red[tid + o];
        __syncthreads();
    }
    if (tid == 0) out[n * NCLS + m] = 0.1f * (float)red[0];
}

// ---------------- launch ----------------
extern "C" void kernel_launch(void* const* d_in, const int* in_sizes, int n_in,
                              void* d_out, int out_size) {
    const float* x   = (const float*)d_in[0];
    const float* w1  = (const float*)d_in[1];
    const float* b1  = (const float*)d_in[2];
    const float* g1  = (const float*)d_in[3];
    const float* be1 = (const float*)d_in[4];
    const float* w2  = (const float*)d_in[5];
    const float* b2  = (const float*)d_in[6];
    const float* g2  = (const float*)d_in[7];
    const float* be2 = (const float*)d_in[8];
    const float* w3  = (const float*)d_in[9];
    const float* b3  = (const float*)d_in[10];
    const float* g3  = (const float*)d_in[11];
    const float* be3 = (const float*)d_in[12];
    const float* w5  = (const float*)d_in[13];
    const float* b5  = (const float*)d_in[14];
    const float* g5  = (const float*)d_in[15];
    const float* be5 = (const float*)d_in[16];
    const float* wfc = (const float*)d_in[17];

    void *p_w2p, *p_w3p, *p_w5p, *p_a1, *p_a2, *p_a3, *p_h1, *p_h2, *p_h3, *p_h5;
    cudaGetSymbolAddress(&p_w2p, g_w2p);
    cudaGetSymbolAddress(&p_w3p, g_w3p);
    cudaGetSymbolAddress(&p_w5p, g_w5p);
    cudaGetSymbolAddress(&p_a1, g_a1);
    cudaGetSymbolAddress(&p_a2, g_a2);
    cudaGetSymbolAddress(&p_a3, g_a3);
    cudaGetSymbolAddress(&p_h1, g_h1);
    cudaGetSymbolAddress(&p_h2, g_h2);
    cudaGetSymbolAddress(&p_h3, g_h3);
    cudaGetSymbolAddress(&p_h5, g_h5);
    float* h1 = (float*)p_h1; float* h2 = (float*)p_h2;
    float* h3 = (float*)p_h3; float* h5 = (float*)p_h5;
    int8_t* a1 = (int8_t*)p_a1; int8_t* a2 = (int8_t*)p_a2; int8_t* a3 = (int8_t*)p_a3;

    // weight prep
    k_prep_w1<<<(C1 * K1 + 255) / 256, 256>>>(w1);
    k_prep_wc<<<(C2 * C2 * K2 + 255) / 256, 256>>>(w2, (int8_t*)p_w2p, C2, C2, K2);
    k_prep_wc<<<(C3 * C2 * K3 + 255) / 256, 256>>>(w3, (int8_t*)p_w3p, C3, C2, K3);
    k_prep_wc<<<(C5 * C3 * K5 + 255) / 256, 256>>>(w5, (int8_t*)p_w5p, C5, C3, K5);
    k_prep_wfc<<<(NCLS * P5 * C5 + 255) / 256, 256>>>(wfc);

    // layer 1
    k_conv1<<<dim3((L1 + 31) / 32, NB), 256>>>(x, b1);
    k_stat1<<<NSLICE, C1>>>(h1, C1, NB * L1);
    k_stat2<<<C1, NSLICE>>>(g1, be1, NB * L1);
    {
        int total4 = NB * P1 * C1 / 4;
        k_binpool<<<(total4 + 255) / 256, 256>>>(h1, a1, C1, L1, P1, total4);
    }
    // layer 2
    k_convbin<C2, C2, K2, 2><<<dim3((L2 + 63) / 64, C2 / 64, NB), 256>>>(
        a1, (const int8_t*)p_w2p, b2, h2, P1, L2);
    k_stat1<<<NSLICE, C2>>>(h2, C2, NB * L2);
    k_stat2<<<C2, NSLICE>>>(g2, be2, NB * L2);
    {
        int total4 = NB * P2 * C2 / 4;
        k_binpool<<<(total4 + 255) / 256, 256>>>(h2, a2, C2, L2, P2, total4);
    }
    // layer 3
    k_convbin<C2, C3, K3, 1><<<dim3((L3 + 63) / 64, C3 / 64, NB), 256>>>(
        a2, (const int8_t*)p_w3p, b3, h3, P2, L3);
    k_stat1<<<NSLICE, C3>>>(h3, C3, NB * L3);
    k_stat2<<<C3, NSLICE>>>(g3, be3, NB * L3);
    {
        int total4 = NB * P3 * C3 / 4;
        k_binpool<<<(total4 + 255) / 256, 256>>>(h3, a3, C3, L3, P3, total4);
    }
    // layer 5
    k_convbin<C3, C5, K5, 2><<<dim3((L5 + 63) / 64, C5 / 64, NB), 256>>>(
        a3, (const int8_t*)p_w5p, b5, h5, P3, L5);
    k_stat1<<<NSLICE, C5>>>(h5, C5, NB * L5);
    k_stat2<<<C5, NSLICE>>>(g5, be5, NB * L5);
    {
        int total4 = NB * P5 * C5 / 4;
        void* p_a5; cudaGetSymbolAddress(&p_a5, g_a5);
        k_binpool<<<(total4 + 255) / 256, 256>>>(h5, (int8_t*)p_a5, C5, L5, P5, total4);
    }
    // fc
    k_fc<<<dim3(NCLS, NB), 256>>>((float*)d_out);
}

// round 4
// speedup vs baseline: 2.5417x; 2.5417x over previous
#include <cuda_runtime.h>
#include <cstdint>

// ---------------- problem dims ----------------
#define NB 64
#define L1_IN 16000
#define C1 128
#define K1 84
#define L1 3980
#define P1 1990
#define L2 1991
#define P2 995
#define L3 994
#define P3 497
#define L5 499
#define P5 249
#define NCLS 35

// ---------------- device scratch ----------------
__device__ float    g_w1t[K1 * C1];                 // [k][c], +-0.1
__device__ uint32_t g_w2p[4 * 4 * 128];             // [(k*W+word)][co]
__device__ uint32_t g_w3p[4 * 4 * 256];
__device__ uint32_t g_w5p[3 * 8 * 512];
__device__ int      g_ws2[128 * 4];                 // weight row sums [co][k]
__device__ int      g_ws3[256 * 4];
__device__ int      g_ws5[512 * 3];
__device__ uint32_t g_wfcp[NCLS * P5 * 16];         // [m][t][word]

__device__ float    g_h1[(size_t)NB * L1 * C1];
__device__ short    g_h2s[(size_t)NB * L2 * 128];
__device__ short    g_h3s[(size_t)NB * L3 * 256];
__device__ short    g_h5s[(size_t)NB * L5 * 512];
__device__ uint32_t g_a1[(size_t)NB * P1 * 4];      // packed +-1 bits [n][t][word]
__device__ uint32_t g_a2[(size_t)NB * P2 * 4];
__device__ uint32_t g_a3[(size_t)NB * P3 * 8];
__device__ uint32_t g_a5[(size_t)NB * P5 * 16];

__device__ float2   g_fpart[128 * 8000];            // conv1 stat partials
__device__ int2     g_ipart[131072];                // binary conv stat partials
__device__ float    g_A[512], g_B[512];             // binarize coeffs per channel

// ---------------- f32x2 helpers ----------------
__device__ __forceinline__ unsigned long long ffma2_(unsigned long long a,
                                                     unsigned long long b,
                                                     unsigned long long c) {
    unsigned long long d;
    asm("fma.rn.f32x2 %0, %1, %2, %3;" : "=l"(d) : "l"(a), "l"(b), "l"(c));
    return d;
}
__device__ __forceinline__ unsigned long long dup2(float v) {
    unsigned long long r;
    asm("mov.b64 %0, {%1, %1};" : "=l"(r) : "f"(v));
    return r;
}
__device__ __forceinline__ void unpack2(unsigned long long v, float& lo, float& hi) {
    asm("mov.b64 {%0, %1}, %2;" : "=f"(lo), "=f"(hi) : "l"(v));
}

// ---------------- weight prep ----------------
__global__ void k_prep_w1t(const float* __restrict__ w1) {
    int i = blockIdx.x * blockDim.x + threadIdx.x;
    if (i >= C1 * K1) return;
    int co = i / K1, k = i % K1;
    g_w1t[k * C1 + co] = (w1[i] >= 0.f) ? 0.1f : -0.1f;
}

// w [co][ci][k] -> gw[(k*W+word)*Cout + co] bit-packed (bit=1 <=> +1)
__global__ void k_prep_wpack(const float* __restrict__ w, uint32_t* __restrict__ gw,
                             int Cout, int Cin, int K) {
    int W = Cin >> 5;
    int i = blockIdx.x * blockDim.x + threadIdx.x;
    if (i >= Cout * K * W) return;
    int co = i % Cout;
    int rest = i / Cout;
    int word = rest % W;
    int k = rest / W;
    uint32_t bits = 0;
    for (int b = 0; b < 32; b++) {
        int ci = word * 32 + b;
        if (w[((size_t)co * Cin + ci) * K + k] >= 0.f) bits |= (1u << b);
    }
    gw[(k * W + word) * Cout + co] = bits;
}

__global__ void k_prep_wsum(const uint32_t* __restrict__ gw, int* __restrict__ gs,
                            int Cout, int K, int W) {
    int i = blockIdx.x * blockDim.x + threadIdx.x;
    if (i >= Cout * K) return;
    int co = i % Cout, k = i / Cout;
    int s = 0;
    for (int word = 0; word < W; word++)
        s += 2 * __popc(gw[(k * W + word) * Cout + co]) - 32;
    gs[co * K + k] = s;
}

// wfc[m][c*P5+t] -> g_wfcp[m][t][word] bits
__global__ void k_prep_wfc(const float* __restrict__ w) {
    int i = blockIdx.x * blockDim.x + threadIdx.x;
    if (i >= NCLS * P5 * 16) return;
    int word = i % 16;
    int rest = i / 16;
    int t = rest % P5;
    int m = rest / P5;
    uint32_t bits = 0;
    for (int b = 0; b < 32; b++) {
        int c = word * 32 + b;
        if (w[(size_t)m * (512 * P5) + (size_t)c * P5 + t] >= 0.f) bits |= (1u << b);
    }
    g_wfcp[((size_t)m * P5 + t) * 16 + word] = bits;
}

// ---------------- conv1: fp32, stride 4, K=84, fused stats ----------------
// sred aliases ws2 (weights dead after MAC loop) to stay under 48KB static smem.
__global__ __launch_bounds__(256) void k_conv1(const float* __restrict__ x,
                                               const float* __restrict__ b1) {
    __shared__ __align__(16) float ws2[K1 * C1];    // [k][c]; reused as sred later
    __shared__ __align__(16) float xs[212];
    int n = blockIdx.y;
    int tb = blockIdx.x * 32;
    int tid = threadIdx.x;

    for (int i = tid; i < K1 * C1; i += 256) ws2[i] = g_w1t[i];
    for (int i = tid; i < 212; i += 256) {
        int xi = tb * 4 + i;
        xs[i] = (xi < L1_IN) ? x[(size_t)n * L1_IN + xi] : 0.f;
    }
    __syncthreads();

    int cg = tid & 31, tg = tid >> 5;
    int c0 = cg * 4, t0 = tg * 4;
    const float4* xf4 = reinterpret_cast<const float4*>(xs);

    unsigned long long acc2[2][4] = {};
#pragma unroll
    for (int k4 = 0; k4 < 21; k4++) {
        float4 xv[4];
#pragma unroll
        for (int i = 0; i < 4; i++) xv[i] = xf4[t0 + i + k4];
#pragma unroll
        for (int j = 0; j < 4; j++) {
            int k = k4 * 4 + j;
            unsigned long long w0 = *reinterpret_cast<const unsigned long long*>(&ws2[k * C1 + c0]);
            unsigned long long w1 = *reinterpret_cast<const unsigned long long*>(&ws2[k * C1 + c0 + 2]);
#pragma unroll
            for (int i = 0; i < 4; i++) {
                unsigned long long xd = dup2(reinterpret_cast<const float*>(xv)[i * 4 + j]);
                acc2[0][i] = ffma2_(w0, xd, acc2[0][i]);
                acc2[1][i] = ffma2_(w1, xd, acc2[1][i]);
            }
        }
    }

    float v[4][4];
#pragma unroll
    for (int i = 0; i < 4; i++) {
        float lo, hi;
        unpack2(acc2[0][i], lo, hi); v[0][i] = lo; v[1][i] = hi;
        unpack2(acc2[1][i], lo, hi); v[2][i] = lo; v[3][i] = hi;
    }
    float4 bb = *reinterpret_cast<const float4*>(&b1[c0]);
    float bv[4] = {bb.x, bb.y, bb.z, bb.w};
    float ssum[4] = {0, 0, 0, 0}, ssq[4] = {0, 0, 0, 0};
#pragma unroll
    for (int i = 0; i < 4; i++) {
        int t = tb + t0 + i;
        if (t < L1) {
            float o0 = v[0][i] + bv[0], o1 = v[1][i] + bv[1];
            float o2 = v[2][i] + bv[2], o3 = v[3][i] + bv[3];
            *reinterpret_cast<float4*>(&g_h1[((size_t)n * L1 + t) * C1 + c0]) =
                make_float4(o0, o1, o2, o3);
            ssum[0] += o0; ssq[0] += o0 * o0;
            ssum[1] += o1; ssq[1] += o1 * o1;
            ssum[2] += o2; ssq[2] += o2 * o2;
            ssum[3] += o3; ssq[3] += o3 * o3;
        }
    }
    // weights are dead now; reuse ws2 storage for the stat reduction
    __syncthreads();
    float2* sred = reinterpret_cast<float2*>(ws2);   // needs 8*128*8 = 8KB << 43KB
#pragma unroll
    for (int j = 0; j < 4; j++) sred[tg * 128 + c0 + j] = make_float2(ssum[j], ssq[j]);
    __syncthreads();
    if (tid < 128) {
        float s = 0.f, q = 0.f;
#pragma unroll
        for (int g = 0; g < 8; g++) { float2 vv = sred[g * 128 + tid]; s += vv.x; q += vv.y; }
        int part = blockIdx.x * 64 + n;
        g_fpart[(size_t)tid * 8000 + part] = make_float2(s, q);
    }
}

// ---------------- stat finalize (fp32 partials) ----------------
__global__ void k_stat2f(const float* __restrict__ gamma, const float* __restrict__ beta,
                         int NPART, double Rinv) {
    __shared__ double ss[256], sq[256];
    int c = blockIdx.x, tid = threadIdx.x;
    double s = 0.0, q = 0.0;
    for (int i = tid; i < NPART; i += 256) {
        float2 vv = g_fpart[(size_t)c * NPART + i];
        s += vv.x; q += vv.y;
    }
    ss[tid] = s; sq[tid] = q;
    __syncthreads();
    for (int o = 128; o > 0; o >>= 1) {
        if (tid < o) { ss[tid] += ss[tid + o]; sq[tid] += sq[tid + o]; }
        __syncthreads();
    }
    if (tid == 0) {
        double mu = ss[0] * Rinv;
        double var = sq[0] * Rinv - mu * mu;
        double inv = rsqrt(var + 1e-5);
        double A = inv * (double)gamma[c];
        g_A[c] = (float)A;
        g_B[c] = (float)((double)beta[c] - mu * A);
    }
}

// ---------------- stat finalize (integer partials) ----------------
__global__ void k_stat2i(const float* __restrict__ bias, const float* __restrict__ gamma,
                         const float* __restrict__ beta, int NPART, double Rinv) {
    __shared__ long long ss[256], sq[256];
    int c = blockIdx.x, tid = threadIdx.x;
    long long s = 0, q = 0;
    for (int i = tid; i < NPART; i += 256) {
        int2 vv = g_ipart[(size_t)c * NPART + i];
        s += vv.x; q += vv.y;
    }
    ss[tid] = s; sq[tid] = q;
    __syncthreads();
    for (int o = 128; o > 0; o >>= 1) {
        if (tid < o) { ss[tid] += ss[tid + o]; sq[tid] += sq[tid + o]; }
        __syncthreads();
    }
    if (tid == 0) {
        double mu_s = (double)ss[0] * Rinv;
        double Es2 = (double)sq[0] * Rinv;
        double var_h = 0.01 * (Es2 - mu_s * mu_s);
        double b = bias[c];
        double mu_h = 0.1 * mu_s + b;
        double inv = rsqrt(var_h + 1e-5);
        double g = gamma[c];
        double A = 0.1 * inv * g;
        double B = (b - mu_h) * inv * g + (double)beta[c];
        g_A[c] = (float)A;
        g_B[c] = (float)B;
    }
}

// ---------------- binarize + pool(2) -> packed bits ----------------
__global__ void k_binpool_f(const float* __restrict__ h, uint32_t* __restrict__ a,
                            int C, int W, int L, int Lo, int nwarp) {
    int gw = blockIdx.x * 8 + (threadIdx.x >> 5);
    if (gw >= nwarp) return;
    int lane = threadIdx.x & 31;
    int word = gw % W;
    int r = gw / W;                          // n*Lo + to
    int to = r % Lo, n = r / Lo;
    int c = word * 32 + lane;
    float A = g_A[c], B = g_B[c];
    size_t base = ((size_t)n * L + 2 * to) * C + c;
    bool p = (fmaf(h[base], A, B) >= 0.f) | (fmaf(h[base + C], A, B) >= 0.f);
    unsigned m = __ballot_sync(0xFFFFFFFFu, p);
    if (lane == 0) a[(size_t)r * W + word] = m;
}

__global__ void k_binpool_i(const short* __restrict__ h, uint32_t* __restrict__ a,
                            int C, int W, int L, int Lo, int nwarp) {
    int gw = blockIdx.x * 8 + (threadIdx.x >> 5);
    if (gw >= nwarp) return;
    int lane = threadIdx.x & 31;
    int word = gw % W;
    int r = gw / W;
    int to = r % Lo, n = r / Lo;
    int c = word * 32 + lane;
    float A = g_A[c], B = g_B[c];
    size_t base = ((size_t)n * L + 2 * to) * C + c;
    float v0 = (float)h[base], v1 = (float)h[base + C];
    bool p = (fmaf(v0, A, B) >= 0.f) | (fmaf(v1, A, B) >= 0.f);
    unsigned m = __ballot_sync(0xFFFFFFFFu, p);
    if (lane == 0) a[(size_t)r * W + word] = m;
}

// ---------------- binary conv via XNOR-popcount, fused int stats ----------------
template <int CIN, int COUT, int K, int PAD>
__global__ __launch_bounds__(256) void k_convp(const uint32_t* __restrict__ a,
                                               const uint32_t* __restrict__ gw,
                                               const int* __restrict__ gs,
                                               short* __restrict__ h,
                                               int Lin, int Lout, int NPART) {
    constexpr int W = CIN / 32;
    constexpr int TT = 128;
    constexpr int AR = TT + K - 1;
    __shared__ __align__(16) uint32_t ws[K * W * 64];
    __shared__ uint32_t as_[AR * W];
    __shared__ int wsum_s[K * 64];
    __shared__ int2 sred[16 * 64];

    int n = blockIdx.z;
    int cob = blockIdx.y * 64;
    int tb = blockIdx.x * TT;
    int tid = threadIdx.x;

    for (int i = tid; i < K * W * 64; i += 256) {
        int co = i & 63, kw = i >> 6;
        ws[i] = gw[kw * COUT + cob + co];
    }
    for (int i = tid; i < K * 64; i += 256) {
        int co = i & 63, k = i >> 6;
        wsum_s[i] = gs[(cob + co) * K + k];
    }
    for (int i = tid; i < AR * W; i += 256) {
        int row = i / W, w = i % W;
        int r = tb + row - PAD;
        as_[i] = (r >= 0 && r < Lin) ? a[((size_t)n * Lin + r) * W + w] : 0xFFFFFFFFu;
    }
    __syncthreads();

    int co0 = (tid & 15) * 4;
    int t0 = (tid >> 4) * 8;
    int acc[4][8] = {};
#pragma unroll
    for (int w = 0; w < W; w++) {
        uint32_t ar[8 + K - 1];
#pragma unroll
        for (int j = 0; j < 8 + K - 1; j++) ar[j] = as_[(t0 + j) * W + w];
#pragma unroll
        for (int k = 0; k < K; k++) {
            uint4 wv = *reinterpret_cast<const uint4*>(&ws[(k * W + w) * 64 + co0]);
#pragma unroll
            for (int i = 0; i < 8; i++) {
                uint32_t av = ar[i + k];
                acc[0][i] += __popc(wv.x ^ av);
                acc[1][i] += __popc(wv.y ^ av);
                acc[2][i] += __popc(wv.z ^ av);
                acc[3][i] += __popc(wv.w ^ av);
            }
        }
    }

    bool bdry = (tb < PAD) || (tb + TT + K - 2 - PAD >= Lin);
    int ssum[4] = {}, ssq[4] = {};
#pragma unroll
    for (int i = 0; i < 8; i++) {
        int t = tb + t0 + i;
        int s0 = K * CIN - 2 * acc[0][i];
        int s1 = K * CIN - 2 * acc[1][i];
        int s2 = K * CIN - 2 * acc[2][i];
        int s3 = K * CIN - 2 * acc[3][i];
        if (bdry) {
#pragma unroll
            for (int k = 0; k < K; k++) {
                int r = t - PAD + k;
                if (r < 0 || r >= Lin) {
                    s0 -= wsum_s[k * 64 + co0 + 0];
                    s1 -= wsum_s[k * 64 + co0 + 1];
                    s2 -= wsum_s[k * 64 + co0 + 2];
                    s3 -= wsum_s[k * 64 + co0 + 3];
                }
            }
        }
        if (t < Lout) {
            *reinterpret_cast<short4*>(&h[((size_t)n * Lout + t) * COUT + cob + co0]) =
                make_short4((short)s0, (short)s1, (short)s2, (short)s3);
            ssum[0] += s0; ssq[0] += s0 * s0;
            ssum[1] += s1; ssq[1] += s1 * s1;
            ssum[2] += s2; ssq[2] += s2 * s2;
            ssum[3] += s3; ssq[3] += s3 * s3;
        }
    }
    int g = tid >> 4;
#pragma unroll
    for (int j = 0; j < 4; j++) sred[g * 64 + co0 + j] = make_int2(ssum[j], ssq[j]);
    __syncthreads();
    if (tid < 64) {
        int s = 0, q = 0;
#pragma unroll
        for (int gg = 0; gg < 16; gg++) { int2 vv = sred[gg * 64 + tid]; s += vv.x; q += vv.y; }
        int part = blockIdx.x * NB + n;
        g_ipart[(size_t)(cob + tid) * NPART + part] = make_int2(s, q);
    }
}

// ---------------- FC via popcount ----------------
__global__ __launch_bounds__(256) void k_fc(float* __restrict__ out) {
    int m = blockIdx.x, n = blockIdx.y, tid = threadIdx.x;
    const uint32_t* av = &g_a5[(size_t)n * P5 * 16];
    const uint32_t* wv = &g_wfcp[(size_t)m * P5 * 16];
    int p = 0;
    for (int i = tid; i < P5 * 16; i += 256) p += __popc(av[i] ^ wv[i]);
    __shared__ int red[256];
    red[tid] = p;
    __syncthreads();
    for (int o = 128; o > 0; o >>= 1) {
        if (tid < o) red[tid] += red[tid + o];
        __syncthreads();
    }
    if (tid == 0) out[n * NCLS + m] = 0.1f * (float)(P5 * 512 - 2 * red[0]);
}

// ---------------- launch ----------------
extern "C" void kernel_launch(void* const* d_in, const int* in_sizes, int n_in,
                              void* d_out, int out_size) {
    const float* x   = (const float*)d_in[0];
    const float* w1  = (const float*)d_in[1];
    const float* b1  = (const float*)d_in[2];
    const float* g1  = (const float*)d_in[3];
    const float* be1 = (const float*)d_in[4];
    const float* w2  = (const float*)d_in[5];
    const float* b2  = (const float*)d_in[6];
    const float* g2  = (const float*)d_in[7];
    const float* be2 = (const float*)d_in[8];
    const float* w3  = (const float*)d_in[9];
    const float* b3  = (const float*)d_in[10];
    const float* g3  = (const float*)d_in[11];
    const float* be3 = (const float*)d_in[12];
    const float* w5  = (const float*)d_in[13];
    const float* b5  = (const float*)d_in[14];
    const float* g5  = (const float*)d_in[15];
    const float* be5 = (const float*)d_in[16];
    const float* wfc = (const float*)d_in[17];

    void *p_w2p, *p_w3p, *p_w5p, *p_ws2, *p_ws3, *p_ws5;
    void *p_a1, *p_a2, *p_a3, *p_a5, *p_h2, *p_h3, *p_h5, *p_h1;
    cudaGetSymbolAddress(&p_w2p, g_w2p);
    cudaGetSymbolAddress(&p_w3p, g_w3p);
    cudaGetSymbolAddress(&p_w5p, g_w5p);
    cudaGetSymbolAddress(&p_ws2, g_ws2);
    cudaGetSymbolAddress(&p_ws3, g_ws3);
    cudaGetSymbolAddress(&p_ws5, g_ws5);
    cudaGetSymbolAddress(&p_a1, g_a1);
    cudaGetSymbolAddress(&p_a2, g_a2);
    cudaGetSymbolAddress(&p_a3, g_a3);
    cudaGetSymbolAddress(&p_a5, g_a5);
    cudaGetSymbolAddress(&p_h1, g_h1);
    cudaGetSymbolAddress(&p_h2, g_h2s);
    cudaGetSymbolAddress(&p_h3, g_h3s);
    cudaGetSymbolAddress(&p_h5, g_h5s);

    // weight prep
    k_prep_w1t<<<(C1 * K1 + 255) / 256, 256>>>(w1);
    k_prep_wpack<<<(128 * 4 * 4 + 255) / 256, 256>>>(w2, (uint32_t*)p_w2p, 128, 128, 4);
    k_prep_wpack<<<(256 * 4 * 4 + 255) / 256, 256>>>(w3, (uint32_t*)p_w3p, 256, 128, 4);
    k_prep_wpack<<<(512 * 3 * 8 + 255) / 256, 256>>>(w5, (uint32_t*)p_w5p, 512, 256, 3);
    k_prep_wsum<<<(128 * 4 + 255) / 256, 256>>>((const uint32_t*)p_w2p, (int*)p_ws2, 128, 4, 4);
    k_prep_wsum<<<(256 * 4 + 255) / 256, 256>>>((const uint32_t*)p_w3p, (int*)p_ws3, 256, 4, 4);
    k_prep_wsum<<<(512 * 3 + 255) / 256, 256>>>((const uint32_t*)p_w5p, (int*)p_ws5, 512, 3, 8);
    k_prep_wfc<<<(NCLS * P5 * 16 + 255) / 256, 256>>>(wfc);

    // layer 1
    k_conv1<<<dim3(125, NB), 256>>>(x, b1);
    k_stat2f<<<C1, 256>>>(g1, be1, 8000, 1.0 / (double)(NB * L1));
    {
        int nw = NB * P1 * 4;
        k_binpool_f<<<(nw + 7) / 8, 256>>>((const float*)p_h1, (uint32_t*)p_a1, 128, 4, L1, P1, nw);
    }
    // layer 2
    k_convp<128, 128, 4, 2><<<dim3(16, 2, NB), 256>>>(
        (const uint32_t*)p_a1, (const uint32_t*)p_w2p, (const int*)p_ws2,
        (short*)p_h2, P1, L2, 16 * NB);
    k_stat2i<<<128, 256>>>(b2, g2, be2, 16 * NB, 1.0 / (double)(NB * L2));
    {
        int nw = NB * P2 * 4;
        k_binpool_i<<<(nw + 7) / 8, 256>>>((const short*)p_h2, (uint32_t*)p_a2, 128, 4, L2, P2, nw);
    }
    // layer 3
    k_convp<128, 256, 4, 1><<<dim3(8, 4, NB), 256>>>(
        (const uint32_t*)p_a2, (const uint32_t*)p_w3p, (const int*)p_ws3,
        (short*)p_h3, P2, L3, 8 * NB);
    k_stat2i<<<256, 256>>>(b3, g3, be3, 8 * NB, 1.0 / (double)(NB * L3));
    {
        int nw = NB * P3 * 8;
        k_binpool_i<<<(nw + 7) / 8, 256>>>((const short*)p_h3, (uint32_t*)p_a3, 256, 8, L3, P3, nw);
    }
    // layer 5
    k_convp<256, 512, 3, 2><<<dim3(4, 8, NB), 256>>>(
        (const uint32_t*)p_a3, (const uint32_t*)p_w5p, (const int*)p_ws5,
        (short*)p_h5, P3, L5, 4 * NB);
    k_stat2i<<<512, 256>>>(b5, g5, be5, 4 * NB, 1.0 / (double)(NB * L5));
    {
        int nw = NB * P5 * 16;
        k_binpool_i<<<(nw + 7) / 8, 256>>>((const short*)p_h5, (uint32_t*)p_a5, 512, 16, L5, P5, nw);
    }
    // fc
    k_fc<<<dim3(NCLS, NB), 256>>>((float*)d_out);
}